// round 3
// baseline (speedup 1.0000x reference)
#include <cuda_runtime.h>
#include <cstdint>

// Problem constants (fixed by the dataset)
#define BATCH 4
#define NCAPS 32          // B_ (output capsule types)
#define CIN   32          // C_
#define KK    3
#define WSP   14
#define HH    16          // 4x4 pose matrix
#define OHW   29
#define CJI   (CIN*WSP*WSP)     // 6272
#define NKL   (NCAPS*KK*KK)     // 288
#define OUT_ELEMS (BATCH*NCAPS*OHW*OHW*HH)   // 1,722,368

// sqrt(var) scratch — allocation-free (__device__ global)
__device__ float g_sv[BATCH*CJI*HH];

__global__ void k_sqrtvar(const float* __restrict__ var) {
    int idx = blockIdx.x*blockDim.x + threadIdx.x;
    const int n4 = BATCH*CJI*HH/4;
    if (idx < n4) {
        float4 v = reinterpret_cast<const float4*>(var)[idx];
        reinterpret_cast<float4*>(g_sv)[idx] =
            make_float4(sqrtf(v.x), sqrtf(v.y), sqrtf(v.z), sqrtf(v.w));
    }
}

__global__ void k_zero(float4* __restrict__ out) {
    int idx = blockIdx.x*blockDim.x + threadIdx.x;
    if (idx < OUT_ELEMS/4) out[idx] = make_float4(0.f,0.f,0.f,0.f);
}

// Main kernel: block = (n, j, b); thread t = kl*14 + i  (126 active of 128).
// Each thread reduces over c=0..31 sequentially in registers:
//   votes(v,w) = fma(sv, noise, mu)             (16 FMA)
//   acc(u,w)  += Wt(u,v) * votes(v,w)           (64 FMA)
// mu/sv/Wt come from shared (staged per block); noise streams via __ldcs.
// Epilogue: 16 float atomicAdds into recon[b,n, 2i+k, 2j+l, :].
__global__ __launch_bounds__(128)
void k_main(const float* __restrict__ poses,
            const float* __restrict__ Wt,
            const float* __restrict__ noise,
            float* __restrict__ out)
{
    const int n = blockIdx.x;
    const int j = blockIdx.y;
    const int b = blockIdx.z;
    const int t = threadIdx.x;

    extern __shared__ float sh[];
    float*  sW   = sh;                                    // [9][32][16] = 4608 floats
    float4* sMu4 = reinterpret_cast<float4*>(sh + 4608);  // [16][14][5] f4 (pitch 20 floats)
    float4* sSv4 = sMu4 + 1120;                           // same layout

    // ---- stage Wt[n] : 4608 floats = 1152 float4, contiguous ----
    {
        const float4* src = reinterpret_cast<const float4*>(Wt) + (size_t)n * 1152;
        float4* dst = reinterpret_cast<float4*>(sW);
        #pragma unroll
        for (int it = 0; it < 9; it++) {
            int idx = t + it*128;
            dst[idx] = __ldg(&src[idx]);
        }
    }

    const int kl = t / 14;           // 0..8
    const int k  = kl / 3;
    const int l  = kl - k*3;
    const int i  = t - kl*14;        // 0..13
    const bool active = (t < 126);

    // noise element offset: ((b*288 + n*9 + kl)*6272 + c*196 + j*14 + i)*16
    const float4* np4 = reinterpret_cast<const float4*>(noise)
        + ((size_t)(b*NKL + n*9 + (active ? kl : 0)) * CJI + (size_t)(j*WSP + i)) * 4;
    // mu element offset: ((b*32 + c)*196 + j*14 + i)*16  -> c stride 784 f4
    const float4* mu_g = reinterpret_cast<const float4*>(poses)
        + ((size_t)b*CIN*WSP*WSP + (size_t)j*WSP) * 4;
    // sv element offset: (b*6272 + c*196 + j*14 + i)*16  -> c stride 784 f4
    const float4* sv_g = reinterpret_cast<const float4*>(g_sv)
        + ((size_t)b*CJI + (size_t)j*WSP) * 4;

    float4 a0 = make_float4(0.f,0.f,0.f,0.f);
    float4 a1 = a0, a2 = a0, a3 = a0;

    #pragma unroll 1
    for (int cp = 0; cp < 2; cp++) {
        __syncthreads();   // previous chunk fully consumed before restage
        // ---- stage mu/sv for channels [cp*16, cp*16+16): 16*14*4 = 896 f4 each ----
        #pragma unroll
        for (int it = 0; it < 7; it++) {
            int idx = t + it*128;
            int c   = idx / 56;
            int rem = idx - c*56;
            int is  = rem >> 2;
            int q   = rem & 3;
            size_t g = (size_t)(cp*16 + c) * 784 + (size_t)(is*4 + q);
            int sidx = (c*14 + is)*5 + q;    // pitch-5 f4 (pad) -> conflict-mitigated
            sMu4[sidx] = __ldg(&mu_g[g]);
            sSv4[sidx] = __ldg(&sv_g[g]);
        }
        __syncthreads();

        if (active) {
            #pragma unroll 2
            for (int cc = 0; cc < 16; cc++) {
                const int c = cp*16 + cc;
                const float4* npc = np4 + (size_t)c * 784;
                float4 nz0 = __ldcs(npc + 0);
                float4 nz1 = __ldcs(npc + 1);
                float4 nz2 = __ldcs(npc + 2);
                float4 nz3 = __ldcs(npc + 3);

                const int sb = (cc*14 + i)*5;
                float4 m0 = sMu4[sb+0], m1 = sMu4[sb+1], m2 = sMu4[sb+2], m3 = sMu4[sb+3];
                float4 s0 = sSv4[sb+0], s1 = sSv4[sb+1], s2 = sSv4[sb+2], s3 = sSv4[sb+3];

                float4 v0, v1, v2, v3;   // votes rows v=0..3 (w components)
                v0.x=fmaf(s0.x,nz0.x,m0.x); v0.y=fmaf(s0.y,nz0.y,m0.y);
                v0.z=fmaf(s0.z,nz0.z,m0.z); v0.w=fmaf(s0.w,nz0.w,m0.w);
                v1.x=fmaf(s1.x,nz1.x,m1.x); v1.y=fmaf(s1.y,nz1.y,m1.y);
                v1.z=fmaf(s1.z,nz1.z,m1.z); v1.w=fmaf(s1.w,nz1.w,m1.w);
                v2.x=fmaf(s2.x,nz2.x,m2.x); v2.y=fmaf(s2.y,nz2.y,m2.y);
                v2.z=fmaf(s2.z,nz2.z,m2.z); v2.w=fmaf(s2.w,nz2.w,m2.w);
                v3.x=fmaf(s3.x,nz3.x,m3.x); v3.y=fmaf(s3.y,nz3.y,m3.y);
                v3.z=fmaf(s3.z,nz3.z,m3.z); v3.w=fmaf(s3.w,nz3.w,m3.w);

                // weights: sW[(kl*32+c)*16 + u*4 + v]; float4 per row u (broadcast LDS)
                const float4* wt = reinterpret_cast<const float4*>(sW) + (kl*32 + c)*4;
                float4 w0 = wt[0], w1 = wt[1], w2 = wt[2], w3 = wt[3];

                // acc(u,:) += Wt(u,0)*v0 + Wt(u,1)*v1 + Wt(u,2)*v2 + Wt(u,3)*v3
                a0.x=fmaf(w0.x,v0.x,a0.x); a0.x=fmaf(w0.y,v1.x,a0.x); a0.x=fmaf(w0.z,v2.x,a0.x); a0.x=fmaf(w0.w,v3.x,a0.x);
                a0.y=fmaf(w0.x,v0.y,a0.y); a0.y=fmaf(w0.y,v1.y,a0.y); a0.y=fmaf(w0.z,v2.y,a0.y); a0.y=fmaf(w0.w,v3.y,a0.y);
                a0.z=fmaf(w0.x,v0.z,a0.z); a0.z=fmaf(w0.y,v1.z,a0.z); a0.z=fmaf(w0.z,v2.z,a0.z); a0.z=fmaf(w0.w,v3.z,a0.z);
                a0.w=fmaf(w0.x,v0.w,a0.w); a0.w=fmaf(w0.y,v1.w,a0.w); a0.w=fmaf(w0.z,v2.w,a0.w); a0.w=fmaf(w0.w,v3.w,a0.w);

                a1.x=fmaf(w1.x,v0.x,a1.x); a1.x=fmaf(w1.y,v1.x,a1.x); a1.x=fmaf(w1.z,v2.x,a1.x); a1.x=fmaf(w1.w,v3.x,a1.x);
                a1.y=fmaf(w1.x,v0.y,a1.y); a1.y=fmaf(w1.y,v1.y,a1.y); a1.y=fmaf(w1.z,v2.y,a1.y); a1.y=fmaf(w1.w,v3.y,a1.y);
                a1.z=fmaf(w1.x,v0.z,a1.z); a1.z=fmaf(w1.y,v1.z,a1.z); a1.z=fmaf(w1.z,v2.z,a1.z); a1.z=fmaf(w1.w,v3.z,a1.z);
                a1.w=fmaf(w1.x,v0.w,a1.w); a1.w=fmaf(w1.y,v1.w,a1.w); a1.w=fmaf(w1.z,v2.w,a1.w); a1.w=fmaf(w1.w,v3.w,a1.w);

                a2.x=fmaf(w2.x,v0.x,a2.x); a2.x=fmaf(w2.y,v1.x,a2.x); a2.x=fmaf(w2.z,v2.x,a2.x); a2.x=fmaf(w2.w,v3.x,a2.x);
                a2.y=fmaf(w2.x,v0.y,a2.y); a2.y=fmaf(w2.y,v1.y,a2.y); a2.y=fmaf(w2.z,v2.y,a2.y); a2.y=fmaf(w2.w,v3.y,a2.y);
                a2.z=fmaf(w2.x,v0.z,a2.z); a2.z=fmaf(w2.y,v1.z,a2.z); a2.z=fmaf(w2.z,v2.z,a2.z); a2.z=fmaf(w2.w,v3.z,a2.z);
                a2.w=fmaf(w2.x,v0.w,a2.w); a2.w=fmaf(w2.y,v1.w,a2.w); a2.w=fmaf(w2.z,v2.w,a2.w); a2.w=fmaf(w2.w,v3.w,a2.w);

                a3.x=fmaf(w3.x,v0.x,a3.x); a3.x=fmaf(w3.y,v1.x,a3.x); a3.x=fmaf(w3.z,v2.x,a3.x); a3.x=fmaf(w3.w,v3.x,a3.x);
                a3.y=fmaf(w3.x,v0.y,a3.y); a3.y=fmaf(w3.y,v1.y,a3.y); a3.y=fmaf(w3.z,v2.y,a3.y); a3.y=fmaf(w3.w,v3.y,a3.y);
                a3.z=fmaf(w3.x,v0.z,a3.z); a3.z=fmaf(w3.y,v1.z,a3.z); a3.z=fmaf(w3.z,v2.z,a3.z); a3.z=fmaf(w3.w,v3.z,a3.z);
                a3.w=fmaf(w3.x,v0.w,a3.w); a3.w=fmaf(w3.y,v1.w,a3.w); a3.w=fmaf(w3.z,v2.w,a3.w); a3.w=fmaf(w3.w,v3.w,a3.w);
            }
        }
    }

    if (active) {
        const int r  = 2*i + k;      // output row    (0..28)
        const int cl = 2*j + l;      // output column (0..28)
        float* dst = out + (((size_t)(b*NCAPS + n)*OHW + r)*OHW + cl)*HH;
        atomicAdd(dst+ 0, a0.x); atomicAdd(dst+ 1, a0.y); atomicAdd(dst+ 2, a0.z); atomicAdd(dst+ 3, a0.w);
        atomicAdd(dst+ 4, a1.x); atomicAdd(dst+ 5, a1.y); atomicAdd(dst+ 6, a1.z); atomicAdd(dst+ 7, a1.w);
        atomicAdd(dst+ 8, a2.x); atomicAdd(dst+ 9, a2.y); atomicAdd(dst+10, a2.z); atomicAdd(dst+11, a2.w);
        atomicAdd(dst+12, a3.x); atomicAdd(dst+13, a3.y); atomicAdd(dst+14, a3.z); atomicAdd(dst+15, a3.w);
    }
}

extern "C" void kernel_launch(void* const* d_in, const int* in_sizes, int n_in,
                              void* d_out, int out_size) {
    const float* poses = (const float*)d_in[0];
    const float* var   = (const float*)d_in[1];
    const float* Wt    = (const float*)d_in[2];
    const float* noise = (const float*)d_in[3];
    float* out = (float*)d_out;
    (void)in_sizes; (void)n_in; (void)out_size;

    const int SMEM = (4608 + 4480 + 4480) * 4;   // 54,272 B
    cudaFuncSetAttribute(k_main, cudaFuncAttributeMaxDynamicSharedMemorySize, SMEM);

    k_zero<<<(OUT_ELEMS/4 + 255)/256, 256>>>((float4*)out);
    k_sqrtvar<<<(BATCH*CJI*HH/4 + 255)/256, 256>>>(var);
    k_main<<<dim3(NCAPS, WSP, BATCH), 128, SMEM>>>(poses, Wt, noise, out);
}